// round 14
// baseline (speedup 1.0000x reference)
#include <cuda_runtime.h>
#include <cuda_bf16.h>
#include <cstdint>

#define NN 50000
#define DD 128
#define NE 800000
#define WFM 32768                     // bytes of one fragment-major bf16 matrix
// layout per matrix m: hi frags [WFM] || lo frags [WFM]

// ---------------- device scratch (no allocations allowed) -------------------
__device__ float g_acc[NN * DD];
__device__ float g_hA[NN * DD];
__device__ float g_hB[NN * DD];
__device__ int   g_cnt[NN + 1];
__device__ int   g_cur[NN];
__device__ int   g_csr[NE];
// 7 matrices, fragment-major: frag[tile=kc*8+np][lane] = uint4 (h0,h1,h2,h3)
__device__ __align__(16) char g_wp[7 * 2 * WFM];

// ---------------- fp32 -> bf16 hi/lo helpers --------------------------------
__device__ __forceinline__ uint32_t pbf2(float a, float b) {
    unsigned short ua = __bfloat16_as_ushort(__float2bfloat16_rn(a));
    unsigned short ub = __bfloat16_as_ushort(__float2bfloat16_rn(b));
    return (uint32_t)ua | ((uint32_t)ub << 16);
}
__device__ __forceinline__ float bres(float a) {
    return a - __bfloat162float(__float2bfloat16_rn(a));
}

// detect int64 vs int32 edge_index (little-endian: int64 high words all zero)
__device__ __forceinline__ int detect64(const unsigned int* __restrict__ w) {
    int is64 = 1;
#pragma unroll
    for (int j = 1; j < 64; j += 2)
        if (w[j] != 0u) { is64 = 0; break; }
    return is64;
}

// ---------------- mma primitive ---------------------------------------------
__device__ __forceinline__ void mma16816(float* c, const uint32_t* a,
                                         uint32_t b0, uint32_t b1) {
    asm volatile(
        "mma.sync.aligned.m16n8k16.row.col.f32.bf16.bf16.f32 "
        "{%0,%1,%2,%3}, {%4,%5,%6,%7}, {%8,%9}, {%0,%1,%2,%3};"
        : "+f"(c[0]), "+f"(c[1]), "+f"(c[2]), "+f"(c[3])
        : "r"(a[0]), "r"(a[1]), "r"(a[2]), "r"(a[3]), "r"(b0), "r"(b1));
}

__device__ __forceinline__ uint32_t smem_u32(const void* p) {
    uint32_t a;
    asm("{ .reg .u64 t; cvta.to.shared.u64 t, %1; cvt.u32.u64 %0, t; }"
        : "=r"(a) : "l"(p));
    return a;
}

// ---------------- preprocessing kernels -------------------------------------
__global__ void hist_k(const unsigned int* __restrict__ w, int* __restrict__ cnt) {
    int is64 = detect64(w);
    int e0 = 4 * (blockIdx.x * blockDim.x + threadIdx.x);
#pragma unroll
    for (int q = 0; q < 4; q++) {
        int e = e0 + q;
        if (e < NE) {
            int d = is64 ? (int)w[2 * (NE + e)] : (int)w[NE + e];
            atomicAdd(&cnt[d + 1], 1);
        }
    }
}

__global__ void scan_k(int* __restrict__ cnt, int* __restrict__ cur) {
    __shared__ int part[1024];
    const int TOT = NN + 1;
    const int CH = (TOT + 1023) / 1024;
    int t = threadIdx.x;
    int beg = t * CH;
    int end = beg + CH; if (end > TOT) end = TOT;
    int sum = 0;
    for (int i = beg; i < end; i++) sum += cnt[i];
    part[t] = sum;
    __syncthreads();
    for (int off = 1; off < 1024; off <<= 1) {
        int add = (t >= off) ? part[t - off] : 0;
        __syncthreads();
        part[t] += add;
        __syncthreads();
    }
    int run = (t == 0) ? 0 : part[t - 1];
    for (int i = beg; i < end; i++) {
        run += cnt[i];
        cnt[i] = run;
        if (i < NN) cur[i] = run;
    }
}

__global__ void fill_k(const unsigned int* __restrict__ w,
                       int* __restrict__ cur, int* __restrict__ csr) {
    int is64 = detect64(w);
    int e0 = 4 * (blockIdx.x * blockDim.x + threadIdx.x);
#pragma unroll
    for (int q = 0; q < 4; q++) {
        int e = e0 + q;
        if (e < NE) {
            int s, d;
            if (is64) { s = (int)w[2 * e]; d = (int)w[2 * (NE + e)]; }
            else      { s = (int)w[e];     d = (int)w[NE + e]; }
            int p = atomicAdd(&cur[d], 1);
            csr[p] = s;
        }
    }
}

// Weight prep: fp32 W[k][n] -> fragment-major bf16 hi/lo (see R13 mapping).
__global__ void prep_w_k(const float* w0, const float* w1, const float* w2,
                         const float* w3, const float* w4, const float* w5,
                         const float* w6, char* __restrict__ wp) {
    const float* ws[7] = {w0, w1, w2, w3, w4, w5, w6};
    int m = blockIdx.y;
    const float* w = ws[m];
    uint4* dhi = (uint4*)(wp + (size_t)m * 2 * WFM);
    uint4* dlo = (uint4*)(wp + (size_t)m * 2 * WFM + WFM);
    int idx = blockIdx.x * 256 + threadIdx.x;   // 0..2047
    int tile = idx >> 5, lane = idx & 31;       // tile 0..63
    int kc = tile >> 3, np = tile & 7;
    int row = np * 16 + (lane >> 2);
    int kb = kc * 16 + 2 * (lane & 3);
    float a0 = w[(kb + 0) * DD + row], a1 = w[(kb + 1) * DD + row];
    float b0 = w[(kb + 8) * DD + row], b1 = w[(kb + 9) * DD + row];
    int row2 = row + 8;
    float c0 = w[(kb + 0) * DD + row2], c1 = w[(kb + 1) * DD + row2];
    float d0 = w[(kb + 8) * DD + row2], d1 = w[(kb + 9) * DD + row2];
    dhi[idx] = make_uint4(pbf2(a0, a1), pbf2(b0, b1), pbf2(c0, c1), pbf2(d0, d1));
    dlo[idx] = make_uint4(pbf2(bres(a0), bres(a1)), pbf2(bres(b0), bres(b1)),
                          pbf2(bres(c0), bres(c1)), pbf2(bres(d0), bres(d1)));
}

// ---------------- aggregation (near L2 gather ceiling) -----------------------
__global__ __launch_bounds__(256) void agg_k(const float* __restrict__ h,
                                             const int* __restrict__ rs,
                                             const int* __restrict__ csr,
                                             float* __restrict__ acc) {
    int warp = threadIdx.x >> 5, lane = threadIdx.x & 31;
    int node = blockIdx.x * 8 + warp;
    if (node >= NN) return;
    float4 a = ((const float4*)(h + (size_t)node * DD))[lane];
    int beg = rs[node], end = rs[node + 1];
#pragma unroll 8
    for (int j = beg; j < end; j++) {
        int s = csr[j];
        float4 v = ((const float4*)(h + (size_t)s * DD))[lane];
        a.x += v.x; a.y += v.y; a.z += v.z; a.w += v.w;
    }
    ((float4*)(acc + (size_t)node * DD))[lane] = a;
}

// ---------------- fragment-direct bf16-split MLP -----------------------------
// Al fragments live in thread-private smem (AB[kc][tid], conflict-free
// LDS.128) so regs fit a 4-blocks/SM occupancy. Same-thread STS->LDS needs
// no synchronization.
__device__ __forceinline__ void al_store(uint32_t ab, int kc, uint32_t w0,
                                         uint32_t w1, uint32_t w2, uint32_t w3) {
    asm volatile("st.shared.v4.u32 [%0], {%1,%2,%3,%4};"
                 :: "r"(ab + kc * 2048), "r"(w0), "r"(w1), "r"(w2), "r"(w3)
                 : "memory");
}

__device__ __forceinline__ void gemm_frag(float c[16][4],
                                          const uint32_t Ah[8][4],
                                          uint32_t ab,
                                          const uint4* __restrict__ Wh,
                                          const uint4* __restrict__ Wl,
                                          int lane) {
#pragma unroll
    for (int kc = 0; kc < 8; kc++) {
        uint32_t Al4[4];
        asm volatile("ld.shared.v4.u32 {%0,%1,%2,%3}, [%4];"
                     : "=r"(Al4[0]), "=r"(Al4[1]), "=r"(Al4[2]), "=r"(Al4[3])
                     : "r"(ab + kc * 2048));
#pragma unroll
        for (int npp = 0; npp < 4; npp++) {
            const int np0 = 2 * npp, np1 = 2 * npp + 1;
            uint4 H0 = Wh[(kc * 8 + np0) * 32 + lane];
            uint4 L0 = Wl[(kc * 8 + np0) * 32 + lane];
            uint4 H1 = Wh[(kc * 8 + np1) * 32 + lane];
            uint4 L1 = Wl[(kc * 8 + np1) * 32 + lane];
            mma16816(c[2 * np0],     Ah[kc], H0.x, H0.y);
            mma16816(c[2 * np0 + 1], Ah[kc], H0.z, H0.w);
            mma16816(c[2 * np1],     Ah[kc], H1.x, H1.y);
            mma16816(c[2 * np1 + 1], Ah[kc], H1.z, H1.w);
            mma16816(c[2 * np0],     Al4, H0.x, H0.y);
            mma16816(c[2 * np0 + 1], Al4, H0.z, H0.w);
            mma16816(c[2 * np1],     Al4, H1.x, H1.y);
            mma16816(c[2 * np1 + 1], Al4, H1.z, H1.w);
            mma16816(c[2 * np0],     Ah[kc], L0.x, L0.y);
            mma16816(c[2 * np0 + 1], Ah[kc], L0.z, L0.w);
            mma16816(c[2 * np1],     Ah[kc], L1.x, L1.y);
            mma16816(c[2 * np1 + 1], Ah[kc], L1.z, L1.w);
        }
    }
}

__global__ __launch_bounds__(128, 4) void mma_mlp_k(
    const float* __restrict__ X, const char* __restrict__ wp,
    int m1, int m2, int m3,
    const float* __restrict__ b1v, const float* __restrict__ b2v,
    const float* __restrict__ b3v,
    const float* __restrict__ RES, float* __restrict__ Y) {
    extern __shared__ char sm[];
    const int tid = threadIdx.x;
    const int lane = tid & 31;
    const int gID = lane >> 2, tig = lane & 3;
    const uint32_t ab = smem_u32(sm) + tid * 16;   // AB[kc][tid] base
    const int rbase = blockIdx.x * 64 + (tid >> 5) * 16;
    const int row0 = rbase + gID, row1 = row0 + 8;
    const bool v0 = row0 < NN, v1 = row1 < NN;

    const uint4* W1h = (const uint4*)(wp + (size_t)m1 * 2 * WFM);
    const uint4* W1l = (const uint4*)(wp + (size_t)m1 * 2 * WFM + WFM);
    const uint4* W2h = (const uint4*)(wp + (size_t)m2 * 2 * WFM);
    const uint4* W2l = (const uint4*)(wp + (size_t)m2 * 2 * WFM + WFM);

    // ---- load & split A (GEMM1 input) from gmem; Al -> smem ----
    uint32_t Ah[8][4];
#pragma unroll
    for (int kc = 0; kc < 8; kc++) {
        const float* x0 = X + (size_t)row0 * DD + kc * 16 + 2 * tig;
        const float* x1 = X + (size_t)row1 * DD + kc * 16 + 2 * tig;
        float2 p0 = v0 ? *(const float2*)x0 : make_float2(0.f, 0.f);
        float2 p1 = v1 ? *(const float2*)x1 : make_float2(0.f, 0.f);
        float2 p2 = v0 ? *(const float2*)(x0 + 8) : make_float2(0.f, 0.f);
        float2 p3 = v1 ? *(const float2*)(x1 + 8) : make_float2(0.f, 0.f);
        Ah[kc][0] = pbf2(p0.x, p0.y);
        Ah[kc][1] = pbf2(p1.x, p1.y);
        Ah[kc][2] = pbf2(p2.x, p2.y);
        Ah[kc][3] = pbf2(p3.x, p3.y);
        al_store(ab, kc,
                 pbf2(bres(p0.x), bres(p0.y)), pbf2(bres(p1.x), bres(p1.y)),
                 pbf2(bres(p2.x), bres(p2.y)), pbf2(bres(p3.x), bres(p3.y)));
    }

    float c[16][4];

    // ---- GEMM1 ----
#pragma unroll
    for (int i = 0; i < 16; i++)
#pragma unroll
        for (int j = 0; j < 4; j++) c[i][j] = 0.f;
    gemm_frag(c, Ah, ab, W1h, W1l, lane);

    // epilogue1: relu(c + b1) -> A' (Ah regs, Al smem)
#pragma unroll
    for (int kc = 0; kc < 8; kc++) {
        uint32_t alw[4];
#pragma unroll
        for (int half = 0; half < 2; half++) {
            int nt = kc * 2 + half;
            float2 b = *(const float2*)(b1v + nt * 8 + 2 * tig);
            float f0 = fmaxf(c[nt][0] + b.x, 0.f);
            float f1 = fmaxf(c[nt][1] + b.y, 0.f);
            float f2 = fmaxf(c[nt][2] + b.x, 0.f);
            float f3 = fmaxf(c[nt][3] + b.y, 0.f);
            Ah[kc][2 * half]     = pbf2(f0, f1);
            Ah[kc][2 * half + 1] = pbf2(f2, f3);
            alw[2 * half]     = pbf2(bres(f0), bres(f1));
            alw[2 * half + 1] = pbf2(bres(f2), bres(f3));
        }
        al_store(ab, kc, alw[0], alw[1], alw[2], alw[3]);
    }

    // ---- GEMM2 ----
#pragma unroll
    for (int i = 0; i < 16; i++)
#pragma unroll
        for (int j = 0; j < 4; j++) c[i][j] = 0.f;
    gemm_frag(c, Ah, ab, W2h, W2l, lane);

    if (m3 >= 0) {
        // epilogue2: A'' = c + b2 (no relu), then head GEMM
#pragma unroll
        for (int kc = 0; kc < 8; kc++) {
            uint32_t alw[4];
#pragma unroll
            for (int half = 0; half < 2; half++) {
                int nt = kc * 2 + half;
                float2 b = *(const float2*)(b2v + nt * 8 + 2 * tig);
                float f0 = c[nt][0] + b.x;
                float f1 = c[nt][1] + b.y;
                float f2 = c[nt][2] + b.x;
                float f3 = c[nt][3] + b.y;
                Ah[kc][2 * half]     = pbf2(f0, f1);
                Ah[kc][2 * half + 1] = pbf2(f2, f3);
                alw[2 * half]     = pbf2(bres(f0), bres(f1));
                alw[2 * half + 1] = pbf2(bres(f2), bres(f3));
            }
            al_store(ab, kc, alw[0], alw[1], alw[2], alw[3]);
        }
        const uint4* W3h = (const uint4*)(wp + (size_t)m3 * 2 * WFM);
        const uint4* W3l = (const uint4*)(wp + (size_t)m3 * 2 * WFM + WFM);
#pragma unroll
        for (int i = 0; i < 16; i++)
#pragma unroll
            for (int j = 0; j < 4; j++) c[i][j] = 0.f;
        gemm_frag(c, Ah, ab, W3h, W3l, lane);
        // final write: c + b3
#pragma unroll
        for (int nt = 0; nt < 16; nt++) {
            float2 b = *(const float2*)(b3v + nt * 8 + 2 * tig);
            int col = nt * 8 + 2 * tig;
            if (v0) *(float2*)(Y + (size_t)row0 * DD + col) =
                make_float2(c[nt][0] + b.x, c[nt][1] + b.y);
            if (v1) *(float2*)(Y + (size_t)row1 * DD + col) =
                make_float2(c[nt][2] + b.x, c[nt][3] + b.y);
        }
    } else {
        // write: c + b2 (+ RES)
#pragma unroll
        for (int nt = 0; nt < 16; nt++) {
            float2 b = *(const float2*)(b2v + nt * 8 + 2 * tig);
            int col = nt * 8 + 2 * tig;
            float o0 = c[nt][0] + b.x, o1 = c[nt][1] + b.y;
            float o2 = c[nt][2] + b.x, o3 = c[nt][3] + b.y;
            if (RES) {
                if (v0) {
                    float2 r = *(const float2*)(RES + (size_t)row0 * DD + col);
                    o0 += r.x; o1 += r.y;
                }
                if (v1) {
                    float2 r = *(const float2*)(RES + (size_t)row1 * DD + col);
                    o2 += r.x; o3 += r.y;
                }
            }
            if (v0) *(float2*)(Y + (size_t)row0 * DD + col) = make_float2(o0, o1);
            if (v1) *(float2*)(Y + (size_t)row1 * DD + col) = make_float2(o2, o3);
        }
    }
}

// ---------------- launch -----------------------------------------------------
extern "C" void kernel_launch(void* const* d_in, const int* in_sizes, int n_in,
                              void* d_out, int out_size) {
    const float* x         = (const float*)d_in[0];
    const unsigned int* ei = (const unsigned int*)d_in[1];
    const float* w1_0 = (const float*)d_in[2];
    const float* b1_0 = (const float*)d_in[3];
    const float* w2_0 = (const float*)d_in[4];
    const float* b2_0 = (const float*)d_in[5];
    const float* w1_1 = (const float*)d_in[6];
    const float* b1_1 = (const float*)d_in[7];
    const float* w2_1 = (const float*)d_in[8];
    const float* b2_1 = (const float*)d_in[9];
    const float* w1_2 = (const float*)d_in[10];
    const float* b1_2 = (const float*)d_in[11];
    const float* w2_2 = (const float*)d_in[12];
    const float* b2_2 = (const float*)d_in[13];
    const float* wh   = (const float*)d_in[14];
    const float* bh   = (const float*)d_in[15];
    float* out = (float*)d_out;

    float *acc, *hA, *hB;
    int *cnt, *cur, *csr;
    char* wp;
    cudaGetSymbolAddress((void**)&acc, g_acc);
    cudaGetSymbolAddress((void**)&hA, g_hA);
    cudaGetSymbolAddress((void**)&hB, g_hB);
    cudaGetSymbolAddress((void**)&cnt, g_cnt);
    cudaGetSymbolAddress((void**)&cur, g_cur);
    cudaGetSymbolAddress((void**)&csr, g_csr);
    cudaGetSymbolAddress((void**)&wp, g_wp);

    const int heB = (NE / 4 + 255) / 256;
    const int agB = (NN + 7) / 8;
    const int mlB = (NN + 63) / 64;   // 782
    const int ABB = 16384;            // Al smem bytes per block

    // --- preprocessing ---
    cudaMemsetAsync(cnt, 0, (NN + 1) * sizeof(int));
    hist_k<<<heB, 256>>>(ei, cnt);
    scan_k<<<1, 1024>>>(cnt, cur);
    fill_k<<<heB, 256>>>(ei, cur, csr);

    // --- layer 0 (residual = x) ---
    agg_k<<<agB, 256>>>(x, cnt, csr, acc);
    prep_w_k<<<dim3(8, 7), 256>>>(w1_0, w2_0, w1_1, w2_1, w1_2, w2_2, wh, wp);
    mma_mlp_k<<<mlB, 128, ABB>>>(acc, wp, 0, 1, -1, b1_0, b2_0, nullptr, x, hA);
    // --- layer 1 (residual = hA) ---
    agg_k<<<agB, 256>>>(hA, cnt, csr, acc);
    mma_mlp_k<<<mlB, 128, ABB>>>(acc, wp, 2, 3, -1, b1_1, b2_1, nullptr, hA, hB);
    // --- layer 2 (no residual) + fused head ---
    agg_k<<<agB, 256>>>(hB, cnt, csr, acc);
    mma_mlp_k<<<mlB, 128, ABB>>>(acc, wp, 4, 5, 6, b1_2, b2_2, bh, nullptr, out);
}

// round 15
// speedup vs baseline: 1.1876x; 1.1876x over previous
#include <cuda_runtime.h>
#include <cuda_bf16.h>
#include <cstdint>

#define NN 50000
#define DD 128
#define NE 800000
#define WFM 32768                     // bytes of one fragment-major bf16 matrix
// layout per matrix m: hi frags [WFM] || lo frags [WFM]

// ---------------- device scratch (no allocations allowed) -------------------
__device__ float g_acc[NN * DD];
__device__ float g_hA[NN * DD];
__device__ float g_hB[NN * DD];
__device__ int   g_cnt[NN + 1];
__device__ int   g_cur[NN];
__device__ int   g_csr[NE];
// 7 matrices, fragment-major: frag[tile=kc*8+np][lane] = uint4 (h0,h1,h2,h3)
__device__ __align__(16) char g_wp[7 * 2 * WFM];

// ---------------- fp32 -> bf16 hi/lo helpers --------------------------------
__device__ __forceinline__ uint32_t pbf2(float a, float b) {
    unsigned short ua = __bfloat16_as_ushort(__float2bfloat16_rn(a));
    unsigned short ub = __bfloat16_as_ushort(__float2bfloat16_rn(b));
    return (uint32_t)ua | ((uint32_t)ub << 16);
}
__device__ __forceinline__ float bres(float a) {
    return a - __bfloat162float(__float2bfloat16_rn(a));
}

// detect int64 vs int32 edge_index (little-endian: int64 high words all zero)
__device__ __forceinline__ int detect64(const unsigned int* __restrict__ w) {
    int is64 = 1;
#pragma unroll
    for (int j = 1; j < 64; j += 2)
        if (w[j] != 0u) { is64 = 0; break; }
    return is64;
}

// ---------------- mma primitive ---------------------------------------------
__device__ __forceinline__ void mma16816(float* c, const uint32_t* a,
                                         uint32_t b0, uint32_t b1) {
    asm volatile(
        "mma.sync.aligned.m16n8k16.row.col.f32.bf16.bf16.f32 "
        "{%0,%1,%2,%3}, {%4,%5,%6,%7}, {%8,%9}, {%0,%1,%2,%3};"
        : "+f"(c[0]), "+f"(c[1]), "+f"(c[2]), "+f"(c[3])
        : "r"(a[0]), "r"(a[1]), "r"(a[2]), "r"(a[3]), "r"(b0), "r"(b1));
}

// ---------------- preprocessing kernels -------------------------------------
__global__ void hist_k(const unsigned int* __restrict__ w, int* __restrict__ cnt) {
    int is64 = detect64(w);
    int e0 = 4 * (blockIdx.x * blockDim.x + threadIdx.x);
#pragma unroll
    for (int q = 0; q < 4; q++) {
        int e = e0 + q;
        if (e < NE) {
            int d = is64 ? (int)w[2 * (NE + e)] : (int)w[NE + e];
            atomicAdd(&cnt[d + 1], 1);
        }
    }
}

__global__ void scan_k(int* __restrict__ cnt, int* __restrict__ cur) {
    __shared__ int part[1024];
    const int TOT = NN + 1;
    const int CH = (TOT + 1023) / 1024;
    int t = threadIdx.x;
    int beg = t * CH;
    int end = beg + CH; if (end > TOT) end = TOT;
    int sum = 0;
    for (int i = beg; i < end; i++) sum += cnt[i];
    part[t] = sum;
    __syncthreads();
    for (int off = 1; off < 1024; off <<= 1) {
        int add = (t >= off) ? part[t - off] : 0;
        __syncthreads();
        part[t] += add;
        __syncthreads();
    }
    int run = (t == 0) ? 0 : part[t - 1];
    for (int i = beg; i < end; i++) {
        run += cnt[i];
        cnt[i] = run;
        if (i < NN) cur[i] = run;
    }
}

__global__ void fill_k(const unsigned int* __restrict__ w,
                       int* __restrict__ cur, int* __restrict__ csr) {
    int is64 = detect64(w);
    int e0 = 4 * (blockIdx.x * blockDim.x + threadIdx.x);
#pragma unroll
    for (int q = 0; q < 4; q++) {
        int e = e0 + q;
        if (e < NE) {
            int s, d;
            if (is64) { s = (int)w[2 * e]; d = (int)w[2 * (NE + e)]; }
            else      { s = (int)w[e];     d = (int)w[NE + e]; }
            int p = atomicAdd(&cur[d], 1);
            csr[p] = s;
        }
    }
}

// Weight prep: fp32 W[k][n] -> fragment-major bf16 hi/lo (see R13 mapping).
__global__ void prep_w_k(const float* w0, const float* w1, const float* w2,
                         const float* w3, const float* w4, const float* w5,
                         const float* w6, char* __restrict__ wp) {
    const float* ws[7] = {w0, w1, w2, w3, w4, w5, w6};
    int m = blockIdx.y;
    const float* w = ws[m];
    uint4* dhi = (uint4*)(wp + (size_t)m * 2 * WFM);
    uint4* dlo = (uint4*)(wp + (size_t)m * 2 * WFM + WFM);
    int idx = blockIdx.x * 256 + threadIdx.x;   // 0..2047
    int tile = idx >> 5, lane = idx & 31;       // tile 0..63
    int kc = tile >> 3, np = tile & 7;
    int row = np * 16 + (lane >> 2);
    int kb = kc * 16 + 2 * (lane & 3);
    float a0 = w[(kb + 0) * DD + row], a1 = w[(kb + 1) * DD + row];
    float b0 = w[(kb + 8) * DD + row], b1 = w[(kb + 9) * DD + row];
    int row2 = row + 8;
    float c0 = w[(kb + 0) * DD + row2], c1 = w[(kb + 1) * DD + row2];
    float d0 = w[(kb + 8) * DD + row2], d1 = w[(kb + 9) * DD + row2];
    dhi[idx] = make_uint4(pbf2(a0, a1), pbf2(b0, b1), pbf2(c0, c1), pbf2(d0, d1));
    dlo[idx] = make_uint4(pbf2(bres(a0), bres(a1)), pbf2(bres(b0), bres(b1)),
                          pbf2(bres(c0), bres(c1)), pbf2(bres(d0), bres(d1)));
}

// ---------------- aggregation: dual accumulators break FADD chains ----------
__global__ __launch_bounds__(256) void agg_k(const float* __restrict__ h,
                                             const int* __restrict__ rs,
                                             const int* __restrict__ csr,
                                             float* __restrict__ acc) {
    int warp = threadIdx.x >> 5, lane = threadIdx.x & 31;
    int node = blockIdx.x * 8 + warp;
    if (node >= NN) return;
    float4 a = ((const float4*)(h + (size_t)node * DD))[lane];
    float4 b = make_float4(0.f, 0.f, 0.f, 0.f);
    int beg = rs[node], end = rs[node + 1];
    int j = beg;
#pragma unroll 4
    for (; j + 1 < end; j += 2) {
        int s0 = csr[j];
        int s1 = csr[j + 1];
        float4 v0 = ((const float4*)(h + (size_t)s0 * DD))[lane];
        float4 v1 = ((const float4*)(h + (size_t)s1 * DD))[lane];
        a.x += v0.x; a.y += v0.y; a.z += v0.z; a.w += v0.w;
        b.x += v1.x; b.y += v1.y; b.z += v1.z; b.w += v1.w;
    }
    if (j < end) {
        int s = csr[j];
        float4 v = ((const float4*)(h + (size_t)s * DD))[lane];
        a.x += v.x; a.y += v.y; a.z += v.z; a.w += v.w;
    }
    a.x += b.x; a.y += b.y; a.z += b.z; a.w += b.w;
    ((float4*)(acc + (size_t)node * DD))[lane] = a;
}

// ---------------- fragment-direct bf16-split MLP (no smem, no syncs) ---------
// 16x128x128 GEMM per warp: C += (Ah+Al)@(Wh+Wl), 3 products; B fragments
// loaded as LDG.128 from fragment-major gmem (L1-resident across warps).
__device__ __forceinline__ void gemm_frag(float c[16][4],
                                          const uint32_t Ah[8][4],
                                          const uint32_t Al[8][4],
                                          const uint4* __restrict__ Wh,
                                          const uint4* __restrict__ Wl,
                                          int lane) {
#pragma unroll
    for (int kc = 0; kc < 8; kc++) {
#pragma unroll
        for (int npp = 0; npp < 4; npp++) {
            const int np0 = 2 * npp, np1 = 2 * npp + 1;
            uint4 H0 = Wh[(kc * 8 + np0) * 32 + lane];
            uint4 L0 = Wl[(kc * 8 + np0) * 32 + lane];
            uint4 H1 = Wh[(kc * 8 + np1) * 32 + lane];
            uint4 L1 = Wl[(kc * 8 + np1) * 32 + lane];
            mma16816(c[2 * np0],     Ah[kc], H0.x, H0.y);
            mma16816(c[2 * np0 + 1], Ah[kc], H0.z, H0.w);
            mma16816(c[2 * np1],     Ah[kc], H1.x, H1.y);
            mma16816(c[2 * np1 + 1], Ah[kc], H1.z, H1.w);
            mma16816(c[2 * np0],     Al[kc], H0.x, H0.y);
            mma16816(c[2 * np0 + 1], Al[kc], H0.z, H0.w);
            mma16816(c[2 * np1],     Al[kc], H1.x, H1.y);
            mma16816(c[2 * np1 + 1], Al[kc], H1.z, H1.w);
            mma16816(c[2 * np0],     Ah[kc], L0.x, L0.y);
            mma16816(c[2 * np0 + 1], Ah[kc], L0.z, L0.w);
            mma16816(c[2 * np1],     Ah[kc], L1.x, L1.y);
            mma16816(c[2 * np1 + 1], Ah[kc], L1.z, L1.w);
        }
    }
}

__global__ __launch_bounds__(128, 3) void mma_mlp_k(
    const float* __restrict__ X, const char* __restrict__ wp,
    int m1, int m2, int m3,
    const float* __restrict__ b1v, const float* __restrict__ b2v,
    const float* __restrict__ b3v,
    const float* __restrict__ RES, float* __restrict__ Y) {
    const int tid = threadIdx.x;
    const int lane = tid & 31;
    const int gID = lane >> 2, tig = lane & 3;
    const int rbase = blockIdx.x * 64 + (tid >> 5) * 16;
    const int row0 = rbase + gID, row1 = row0 + 8;
    const bool v0 = row0 < NN, v1 = row1 < NN;

    const uint4* W1h = (const uint4*)(wp + (size_t)m1 * 2 * WFM);
    const uint4* W1l = (const uint4*)(wp + (size_t)m1 * 2 * WFM + WFM);
    const uint4* W2h = (const uint4*)(wp + (size_t)m2 * 2 * WFM);
    const uint4* W2l = (const uint4*)(wp + (size_t)m2 * 2 * WFM + WFM);

    // ---- load & split A (GEMM1 input) from gmem ----
    uint32_t Ah[8][4], Al[8][4];
#pragma unroll
    for (int kc = 0; kc < 8; kc++) {
        const float* x0 = X + (size_t)row0 * DD + kc * 16 + 2 * tig;
        const float* x1 = X + (size_t)row1 * DD + kc * 16 + 2 * tig;
        float2 p0 = v0 ? *(const float2*)x0 : make_float2(0.f, 0.f);
        float2 p1 = v1 ? *(const float2*)x1 : make_float2(0.f, 0.f);
        float2 p2 = v0 ? *(const float2*)(x0 + 8) : make_float2(0.f, 0.f);
        float2 p3 = v1 ? *(const float2*)(x1 + 8) : make_float2(0.f, 0.f);
        Ah[kc][0] = pbf2(p0.x, p0.y); Al[kc][0] = pbf2(bres(p0.x), bres(p0.y));
        Ah[kc][1] = pbf2(p1.x, p1.y); Al[kc][1] = pbf2(bres(p1.x), bres(p1.y));
        Ah[kc][2] = pbf2(p2.x, p2.y); Al[kc][2] = pbf2(bres(p2.x), bres(p2.y));
        Ah[kc][3] = pbf2(p3.x, p3.y); Al[kc][3] = pbf2(bres(p3.x), bres(p3.y));
    }

    float c[16][4];

    // ---- GEMM1 ----
#pragma unroll
    for (int i = 0; i < 16; i++)
#pragma unroll
        for (int j = 0; j < 4; j++) c[i][j] = 0.f;
    gemm_frag(c, Ah, Al, W1h, W1l, lane);

    // epilogue1: relu(c + b1) -> A' (registers only)
#pragma unroll
    for (int nt = 0; nt < 16; nt++) {
        float2 b = *(const float2*)(b1v + nt * 8 + 2 * tig);
        float f0 = fmaxf(c[nt][0] + b.x, 0.f);
        float f1 = fmaxf(c[nt][1] + b.y, 0.f);
        float f2 = fmaxf(c[nt][2] + b.x, 0.f);
        float f3 = fmaxf(c[nt][3] + b.y, 0.f);
        int kc = nt >> 1, s = (nt & 1) * 2;
        Ah[kc][s]     = pbf2(f0, f1); Al[kc][s]     = pbf2(bres(f0), bres(f1));
        Ah[kc][s + 1] = pbf2(f2, f3); Al[kc][s + 1] = pbf2(bres(f2), bres(f3));
    }

    // ---- GEMM2 ----
#pragma unroll
    for (int i = 0; i < 16; i++)
#pragma unroll
        for (int j = 0; j < 4; j++) c[i][j] = 0.f;
    gemm_frag(c, Ah, Al, W2h, W2l, lane);

    if (m3 >= 0) {
        // epilogue2: A'' = c + b2 (no relu), then head GEMM
#pragma unroll
        for (int nt = 0; nt < 16; nt++) {
            float2 b = *(const float2*)(b2v + nt * 8 + 2 * tig);
            float f0 = c[nt][0] + b.x;
            float f1 = c[nt][1] + b.y;
            float f2 = c[nt][2] + b.x;
            float f3 = c[nt][3] + b.y;
            int kc = nt >> 1, s = (nt & 1) * 2;
            Ah[kc][s]     = pbf2(f0, f1); Al[kc][s]     = pbf2(bres(f0), bres(f1));
            Ah[kc][s + 1] = pbf2(f2, f3); Al[kc][s + 1] = pbf2(bres(f2), bres(f3));
        }
        const uint4* W3h = (const uint4*)(wp + (size_t)m3 * 2 * WFM);
        const uint4* W3l = (const uint4*)(wp + (size_t)m3 * 2 * WFM + WFM);
#pragma unroll
        for (int i = 0; i < 16; i++)
#pragma unroll
            for (int j = 0; j < 4; j++) c[i][j] = 0.f;
        gemm_frag(c, Ah, Al, W3h, W3l, lane);
        // final write: c + b3
#pragma unroll
        for (int nt = 0; nt < 16; nt++) {
            float2 b = *(const float2*)(b3v + nt * 8 + 2 * tig);
            int col = nt * 8 + 2 * tig;
            if (v0) *(float2*)(Y + (size_t)row0 * DD + col) =
                make_float2(c[nt][0] + b.x, c[nt][1] + b.y);
            if (v1) *(float2*)(Y + (size_t)row1 * DD + col) =
                make_float2(c[nt][2] + b.x, c[nt][3] + b.y);
        }
    } else {
        // write: c + b2 (+ RES)
#pragma unroll
        for (int nt = 0; nt < 16; nt++) {
            float2 b = *(const float2*)(b2v + nt * 8 + 2 * tig);
            int col = nt * 8 + 2 * tig;
            float o0 = c[nt][0] + b.x, o1 = c[nt][1] + b.y;
            float o2 = c[nt][2] + b.x, o3 = c[nt][3] + b.y;
            if (RES) {
                if (v0) {
                    float2 r = *(const float2*)(RES + (size_t)row0 * DD + col);
                    o0 += r.x; o1 += r.y;
                }
                if (v1) {
                    float2 r = *(const float2*)(RES + (size_t)row1 * DD + col);
                    o2 += r.x; o3 += r.y;
                }
            }
            if (v0) *(float2*)(Y + (size_t)row0 * DD + col) = make_float2(o0, o1);
            if (v1) *(float2*)(Y + (size_t)row1 * DD + col) = make_float2(o2, o3);
        }
    }
}

// ---------------- launch -----------------------------------------------------
extern "C" void kernel_launch(void* const* d_in, const int* in_sizes, int n_in,
                              void* d_out, int out_size) {
    const float* x         = (const float*)d_in[0];
    const unsigned int* ei = (const unsigned int*)d_in[1];
    const float* w1_0 = (const float*)d_in[2];
    const float* b1_0 = (const float*)d_in[3];
    const float* w2_0 = (const float*)d_in[4];
    const float* b2_0 = (const float*)d_in[5];
    const float* w1_1 = (const float*)d_in[6];
    const float* b1_1 = (const float*)d_in[7];
    const float* w2_1 = (const float*)d_in[8];
    const float* b2_1 = (const float*)d_in[9];
    const float* w1_2 = (const float*)d_in[10];
    const float* b1_2 = (const float*)d_in[11];
    const float* w2_2 = (const float*)d_in[12];
    const float* b2_2 = (const float*)d_in[13];
    const float* wh   = (const float*)d_in[14];
    const float* bh   = (const float*)d_in[15];
    float* out = (float*)d_out;

    float *acc, *hA, *hB;
    int *cnt, *cur, *csr;
    char* wp;
    cudaGetSymbolAddress((void**)&acc, g_acc);
    cudaGetSymbolAddress((void**)&hA, g_hA);
    cudaGetSymbolAddress((void**)&hB, g_hB);
    cudaGetSymbolAddress((void**)&cnt, g_cnt);
    cudaGetSymbolAddress((void**)&cur, g_cur);
    cudaGetSymbolAddress((void**)&csr, g_csr);
    cudaGetSymbolAddress((void**)&wp, g_wp);

    const int heB = (NE / 4 + 255) / 256;
    const int agB = (NN + 7) / 8;
    const int mlB = (NN + 63) / 64;   // 782

    // --- preprocessing ---
    cudaMemsetAsync(cnt, 0, (NN + 1) * sizeof(int));
    hist_k<<<heB, 256>>>(ei, cnt);
    scan_k<<<1, 1024>>>(cnt, cur);
    fill_k<<<heB, 256>>>(ei, cur, csr);

    // --- layer 0 (residual = x) ---
    agg_k<<<agB, 256>>>(x, cnt, csr, acc);
    prep_w_k<<<dim3(8, 7), 256>>>(w1_0, w2_0, w1_1, w2_1, w1_2, w2_2, wh, wp);
    mma_mlp_k<<<mlB, 128>>>(acc, wp, 0, 1, -1, b1_0, b2_0, nullptr, x, hA);
    // --- layer 1 (residual = hA) ---
    agg_k<<<agB, 256>>>(hA, cnt, csr, acc);
    mma_mlp_k<<<mlB, 128>>>(acc, wp, 2, 3, -1, b1_1, b2_1, nullptr, hA, hB);
    // --- layer 2 (no residual) + fused head ---
    agg_k<<<agB, 256>>>(hB, cnt, csr, acc);
    mma_mlp_k<<<mlB, 128>>>(acc, wp, 4, 5, 6, b1_2, b2_2, bh, nullptr, out);
}

// round 16
// speedup vs baseline: 1.2222x; 1.0291x over previous
#include <cuda_runtime.h>
#include <cuda_bf16.h>
#include <cstdint>

#define NN 50000
#define DD 128
#define NE 800000
#define WFM 32768                     // bytes of one fragment-major bf16 matrix
#define FEB 782                       // fill blocks (NE/4/256)
// layout per matrix m: hi frags [WFM] || lo frags [WFM]

// ---------------- device scratch (no allocations allowed) -------------------
__device__ float g_acc[NN * DD];
__device__ float g_hA[NN * DD];
__device__ float g_hB[NN * DD];
__device__ int   g_cnt[NN + 1];
__device__ int   g_cur[NN];
__device__ int   g_csr[NE];
// 7 matrices, fragment-major: frag[tile=kc*8+np][lane] = uint4 (h0,h1,h2,h3)
__device__ __align__(16) char g_wp[7 * 2 * WFM];

// ---------------- fp32 -> bf16 hi/lo helpers --------------------------------
__device__ __forceinline__ uint32_t pbf2(float a, float b) {
    unsigned short ua = __bfloat16_as_ushort(__float2bfloat16_rn(a));
    unsigned short ub = __bfloat16_as_ushort(__float2bfloat16_rn(b));
    return (uint32_t)ua | ((uint32_t)ub << 16);
}
__device__ __forceinline__ float bres(float a) {
    return a - __bfloat162float(__float2bfloat16_rn(a));
}

// detect int64 vs int32 edge_index (little-endian: int64 high words all zero)
__device__ __forceinline__ int detect64(const unsigned int* __restrict__ w) {
    int is64 = 1;
#pragma unroll
    for (int j = 1; j < 64; j += 2)
        if (w[j] != 0u) { is64 = 0; break; }
    return is64;
}

// ---------------- mma primitive ---------------------------------------------
__device__ __forceinline__ void mma16816(float* c, const uint32_t* a,
                                         uint32_t b0, uint32_t b1) {
    asm volatile(
        "mma.sync.aligned.m16n8k16.row.col.f32.bf16.bf16.f32 "
        "{%0,%1,%2,%3}, {%4,%5,%6,%7}, {%8,%9}, {%0,%1,%2,%3};"
        : "+f"(c[0]), "+f"(c[1]), "+f"(c[2]), "+f"(c[3])
        : "r"(a[0]), "r"(a[1]), "r"(a[2]), "r"(a[3]), "r"(b0), "r"(b1));
}

// ---------------- preprocessing kernels -------------------------------------
__global__ void hist_k(const unsigned int* __restrict__ w, int* __restrict__ cnt) {
    int is64 = detect64(w);
    int e0 = 4 * (blockIdx.x * blockDim.x + threadIdx.x);
#pragma unroll
    for (int q = 0; q < 4; q++) {
        int e = e0 + q;
        if (e < NE) {
            int d = is64 ? (int)w[2 * (NE + e)] : (int)w[NE + e];
            atomicAdd(&cnt[d + 1], 1);
        }
    }
}

__global__ void scan_k(int* __restrict__ cnt, int* __restrict__ cur) {
    __shared__ int part[1024];
    const int TOT = NN + 1;
    const int CH = (TOT + 1023) / 1024;
    int t = threadIdx.x;
    int beg = t * CH;
    int end = beg + CH; if (end > TOT) end = TOT;
    int sum = 0;
    for (int i = beg; i < end; i++) sum += cnt[i];
    part[t] = sum;
    __syncthreads();
    for (int off = 1; off < 1024; off <<= 1) {
        int add = (t >= off) ? part[t - off] : 0;
        __syncthreads();
        part[t] += add;
        __syncthreads();
    }
    int run = (t == 0) ? 0 : part[t - 1];
    for (int i = beg; i < end; i++) {
        run += cnt[i];
        cnt[i] = run;
        if (i < NN) cur[i] = run;
    }
}

// Fused: blocks [0, FEB) fill CSR; blocks [FEB, FEB+56) prep weights
// (fragment-major bf16 hi/lo, see R13 mapping). Disjoint work, one launch.
__global__ void fill_prep_k(const unsigned int* __restrict__ w,
                            int* __restrict__ cur, int* __restrict__ csr,
                            const float* w0, const float* w1, const float* w2,
                            const float* w3, const float* w4, const float* w5,
                            const float* w6, char* __restrict__ wp) {
    int b = blockIdx.x;
    if (b < FEB) {
        int is64 = detect64(w);
        int e0 = 4 * (b * blockDim.x + threadIdx.x);
#pragma unroll
        for (int q = 0; q < 4; q++) {
            int e = e0 + q;
            if (e < NE) {
                int s, d;
                if (is64) { s = (int)w[2 * e]; d = (int)w[2 * (NE + e)]; }
                else      { s = (int)w[e];     d = (int)w[NE + e]; }
                int p = atomicAdd(&cur[d], 1);
                csr[p] = s;
            }
        }
    } else {
        int pb = b - FEB;               // 0..55
        int m = pb >> 3;                // matrix 0..6
        const float* ws[7] = {w0, w1, w2, w3, w4, w5, w6};
        const float* wsrc = ws[m];
        uint4* dhi = (uint4*)(wp + (size_t)m * 2 * WFM);
        uint4* dlo = (uint4*)(wp + (size_t)m * 2 * WFM + WFM);
        int idx = (pb & 7) * 256 + threadIdx.x;   // 0..2047
        int tile = idx >> 5, lane = idx & 31;     // tile 0..63
        int kc = tile >> 3, np = tile & 7;
        int row = np * 16 + (lane >> 2);
        int kb = kc * 16 + 2 * (lane & 3);
        float a0 = wsrc[(kb + 0) * DD + row], a1 = wsrc[(kb + 1) * DD + row];
        float b0 = wsrc[(kb + 8) * DD + row], b1 = wsrc[(kb + 9) * DD + row];
        int row2 = row + 8;
        float c0 = wsrc[(kb + 0) * DD + row2], c1 = wsrc[(kb + 1) * DD + row2];
        float d0 = wsrc[(kb + 8) * DD + row2], d1 = wsrc[(kb + 9) * DD + row2];
        dhi[idx] = make_uint4(pbf2(a0, a1), pbf2(b0, b1), pbf2(c0, c1), pbf2(d0, d1));
        dlo[idx] = make_uint4(pbf2(bres(a0), bres(a1)), pbf2(bres(b0), bres(b1)),
                              pbf2(bres(c0), bres(c1)), pbf2(bres(d0), bres(d1)));
    }
}

// ---------------- aggregation (R10 config: best measured 27.5us) -------------
__global__ __launch_bounds__(256) void agg_k(const float* __restrict__ h,
                                             const int* __restrict__ rs,
                                             const int* __restrict__ csr,
                                             float* __restrict__ acc) {
    int warp = threadIdx.x >> 5, lane = threadIdx.x & 31;
    int node = blockIdx.x * 8 + warp;
    if (node >= NN) return;
    float4 a = ((const float4*)(h + (size_t)node * DD))[lane];
    int beg = rs[node], end = rs[node + 1];
#pragma unroll 4
    for (int j = beg; j < end; j++) {
        int s = csr[j];
        float4 v = ((const float4*)(h + (size_t)s * DD))[lane];
        a.x += v.x; a.y += v.y; a.z += v.z; a.w += v.w;
    }
    ((float4*)(acc + (size_t)node * DD))[lane] = a;
}

// ---------------- fragment-direct bf16-split MLP (no smem, no syncs) ---------
// 16x128x128 GEMM per warp: C += (Ah+Al)@(Wh+Wl), 3 products; B fragments
// loaded as LDG.128 from fragment-major gmem (L1-resident across warps).
__device__ __forceinline__ void gemm_frag(float c[16][4],
                                          const uint32_t Ah[8][4],
                                          const uint32_t Al[8][4],
                                          const uint4* __restrict__ Wh,
                                          const uint4* __restrict__ Wl,
                                          int lane) {
#pragma unroll
    for (int kc = 0; kc < 8; kc++) {
#pragma unroll
        for (int npp = 0; npp < 4; npp++) {
            const int np0 = 2 * npp, np1 = 2 * npp + 1;
            uint4 H0 = Wh[(kc * 8 + np0) * 32 + lane];
            uint4 L0 = Wl[(kc * 8 + np0) * 32 + lane];
            uint4 H1 = Wh[(kc * 8 + np1) * 32 + lane];
            uint4 L1 = Wl[(kc * 8 + np1) * 32 + lane];
            mma16816(c[2 * np0],     Ah[kc], H0.x, H0.y);
            mma16816(c[2 * np0 + 1], Ah[kc], H0.z, H0.w);
            mma16816(c[2 * np1],     Ah[kc], H1.x, H1.y);
            mma16816(c[2 * np1 + 1], Ah[kc], H1.z, H1.w);
            mma16816(c[2 * np0],     Al[kc], H0.x, H0.y);
            mma16816(c[2 * np0 + 1], Al[kc], H0.z, H0.w);
            mma16816(c[2 * np1],     Al[kc], H1.x, H1.y);
            mma16816(c[2 * np1 + 1], Al[kc], H1.z, H1.w);
            mma16816(c[2 * np0],     Ah[kc], L0.x, L0.y);
            mma16816(c[2 * np0 + 1], Ah[kc], L0.z, L0.w);
            mma16816(c[2 * np1],     Ah[kc], L1.x, L1.y);
            mma16816(c[2 * np1 + 1], Ah[kc], L1.z, L1.w);
        }
    }
}

__global__ __launch_bounds__(128, 3) void mma_mlp_k(
    const float* __restrict__ X, const char* __restrict__ wp,
    int m1, int m2, int m3,
    const float* __restrict__ b1v, const float* __restrict__ b2v,
    const float* __restrict__ b3v,
    const float* __restrict__ RES, float* __restrict__ Y) {
    const int tid = threadIdx.x;
    const int lane = tid & 31;
    const int gID = lane >> 2, tig = lane & 3;
    const int rbase = blockIdx.x * 64 + (tid >> 5) * 16;
    const int row0 = rbase + gID, row1 = row0 + 8;
    const bool v0 = row0 < NN, v1 = row1 < NN;

    const uint4* W1h = (const uint4*)(wp + (size_t)m1 * 2 * WFM);
    const uint4* W1l = (const uint4*)(wp + (size_t)m1 * 2 * WFM + WFM);
    const uint4* W2h = (const uint4*)(wp + (size_t)m2 * 2 * WFM);
    const uint4* W2l = (const uint4*)(wp + (size_t)m2 * 2 * WFM + WFM);

    // ---- load & split A (GEMM1 input) from gmem ----
    uint32_t Ah[8][4], Al[8][4];
#pragma unroll
    for (int kc = 0; kc < 8; kc++) {
        const float* x0 = X + (size_t)row0 * DD + kc * 16 + 2 * tig;
        const float* x1 = X + (size_t)row1 * DD + kc * 16 + 2 * tig;
        float2 p0 = v0 ? *(const float2*)x0 : make_float2(0.f, 0.f);
        float2 p1 = v1 ? *(const float2*)x1 : make_float2(0.f, 0.f);
        float2 p2 = v0 ? *(const float2*)(x0 + 8) : make_float2(0.f, 0.f);
        float2 p3 = v1 ? *(const float2*)(x1 + 8) : make_float2(0.f, 0.f);
        Ah[kc][0] = pbf2(p0.x, p0.y); Al[kc][0] = pbf2(bres(p0.x), bres(p0.y));
        Ah[kc][1] = pbf2(p1.x, p1.y); Al[kc][1] = pbf2(bres(p1.x), bres(p1.y));
        Ah[kc][2] = pbf2(p2.x, p2.y); Al[kc][2] = pbf2(bres(p2.x), bres(p2.y));
        Ah[kc][3] = pbf2(p3.x, p3.y); Al[kc][3] = pbf2(bres(p3.x), bres(p3.y));
    }

    float c[16][4];

    // ---- GEMM1 ----
#pragma unroll
    for (int i = 0; i < 16; i++)
#pragma unroll
        for (int j = 0; j < 4; j++) c[i][j] = 0.f;
    gemm_frag(c, Ah, Al, W1h, W1l, lane);

    // epilogue1: relu(c + b1) -> A' (registers only)
#pragma unroll
    for (int nt = 0; nt < 16; nt++) {
        float2 b = *(const float2*)(b1v + nt * 8 + 2 * tig);
        float f0 = fmaxf(c[nt][0] + b.x, 0.f);
        float f1 = fmaxf(c[nt][1] + b.y, 0.f);
        float f2 = fmaxf(c[nt][2] + b.x, 0.f);
        float f3 = fmaxf(c[nt][3] + b.y, 0.f);
        int kc = nt >> 1, s = (nt & 1) * 2;
        Ah[kc][s]     = pbf2(f0, f1); Al[kc][s]     = pbf2(bres(f0), bres(f1));
        Ah[kc][s + 1] = pbf2(f2, f3); Al[kc][s + 1] = pbf2(bres(f2), bres(f3));
    }

    // ---- GEMM2 ----
#pragma unroll
    for (int i = 0; i < 16; i++)
#pragma unroll
        for (int j = 0; j < 4; j++) c[i][j] = 0.f;
    gemm_frag(c, Ah, Al, W2h, W2l, lane);

    if (m3 >= 0) {
        // epilogue2: A'' = c + b2 (no relu), then head GEMM
#pragma unroll
        for (int nt = 0; nt < 16; nt++) {
            float2 b = *(const float2*)(b2v + nt * 8 + 2 * tig);
            float f0 = c[nt][0] + b.x;
            float f1 = c[nt][1] + b.y;
            float f2 = c[nt][2] + b.x;
            float f3 = c[nt][3] + b.y;
            int kc = nt >> 1, s = (nt & 1) * 2;
            Ah[kc][s]     = pbf2(f0, f1); Al[kc][s]     = pbf2(bres(f0), bres(f1));
            Ah[kc][s + 1] = pbf2(f2, f3); Al[kc][s + 1] = pbf2(bres(f2), bres(f3));
        }
        const uint4* W3h = (const uint4*)(wp + (size_t)m3 * 2 * WFM);
        const uint4* W3l = (const uint4*)(wp + (size_t)m3 * 2 * WFM + WFM);
#pragma unroll
        for (int i = 0; i < 16; i++)
#pragma unroll
            for (int j = 0; j < 4; j++) c[i][j] = 0.f;
        gemm_frag(c, Ah, Al, W3h, W3l, lane);
        // final write: c + b3
#pragma unroll
        for (int nt = 0; nt < 16; nt++) {
            float2 b = *(const float2*)(b3v + nt * 8 + 2 * tig);
            int col = nt * 8 + 2 * tig;
            if (v0) *(float2*)(Y + (size_t)row0 * DD + col) =
                make_float2(c[nt][0] + b.x, c[nt][1] + b.y);
            if (v1) *(float2*)(Y + (size_t)row1 * DD + col) =
                make_float2(c[nt][2] + b.x, c[nt][3] + b.y);
        }
    } else {
        // write: c + b2 (+ RES)
#pragma unroll
        for (int nt = 0; nt < 16; nt++) {
            float2 b = *(const float2*)(b2v + nt * 8 + 2 * tig);
            int col = nt * 8 + 2 * tig;
            float o0 = c[nt][0] + b.x, o1 = c[nt][1] + b.y;
            float o2 = c[nt][2] + b.x, o3 = c[nt][3] + b.y;
            if (RES) {
                if (v0) {
                    float2 r = *(const float2*)(RES + (size_t)row0 * DD + col);
                    o0 += r.x; o1 += r.y;
                }
                if (v1) {
                    float2 r = *(const float2*)(RES + (size_t)row1 * DD + col);
                    o2 += r.x; o3 += r.y;
                }
            }
            if (v0) *(float2*)(Y + (size_t)row0 * DD + col) = make_float2(o0, o1);
            if (v1) *(float2*)(Y + (size_t)row1 * DD + col) = make_float2(o2, o3);
        }
    }
}

// ---------------- launch -----------------------------------------------------
extern "C" void kernel_launch(void* const* d_in, const int* in_sizes, int n_in,
                              void* d_out, int out_size) {
    const float* x         = (const float*)d_in[0];
    const unsigned int* ei = (const unsigned int*)d_in[1];
    const float* w1_0 = (const float*)d_in[2];
    const float* b1_0 = (const float*)d_in[3];
    const float* w2_0 = (const float*)d_in[4];
    const float* b2_0 = (const float*)d_in[5];
    const float* w1_1 = (const float*)d_in[6];
    const float* b1_1 = (const float*)d_in[7];
    const float* w2_1 = (const float*)d_in[8];
    const float* b2_1 = (const float*)d_in[9];
    const float* w1_2 = (const float*)d_in[10];
    const float* b1_2 = (const float*)d_in[11];
    const float* w2_2 = (const float*)d_in[12];
    const float* b2_2 = (const float*)d_in[13];
    const float* wh   = (const float*)d_in[14];
    const float* bh   = (const float*)d_in[15];
    float* out = (float*)d_out;

    float *acc, *hA, *hB;
    int *cnt, *cur, *csr;
    char* wp;
    cudaGetSymbolAddress((void**)&acc, g_acc);
    cudaGetSymbolAddress((void**)&hA, g_hA);
    cudaGetSymbolAddress((void**)&hB, g_hB);
    cudaGetSymbolAddress((void**)&cnt, g_cnt);
    cudaGetSymbolAddress((void**)&cur, g_cur);
    cudaGetSymbolAddress((void**)&csr, g_csr);
    cudaGetSymbolAddress((void**)&wp, g_wp);

    const int heB = (NE / 4 + 255) / 256;
    const int agB = (NN + 7) / 8;
    const int mlB = (NN + 63) / 64;   // 782

    // --- preprocessing (fill + weight prep fused into one launch) ---
    cudaMemsetAsync(cnt, 0, (NN + 1) * sizeof(int));
    hist_k<<<heB, 256>>>(ei, cnt);
    scan_k<<<1, 1024>>>(cnt, cur);
    fill_prep_k<<<FEB + 56, 256>>>(ei, cur, csr,
                                   w1_0, w2_0, w1_1, w2_1, w1_2, w2_2, wh, wp);

    // --- layer 0 (residual = x) ---
    agg_k<<<agB, 256>>>(x, cnt, csr, acc);
    mma_mlp_k<<<mlB, 128>>>(acc, wp, 0, 1, -1, b1_0, b2_0, nullptr, x, hA);
    // --- layer 1 (residual = hA) ---
    agg_k<<<agB, 256>>>(hA, cnt, csr, acc);
    mma_mlp_k<<<mlB, 128>>>(acc, wp, 2, 3, -1, b1_1, b2_1, nullptr, hA, hB);
    // --- layer 2 (no residual) + fused head ---
    agg_k<<<agB, 256>>>(hB, cnt, csr, acc);
    mma_mlp_k<<<mlB, 128>>>(acc, wp, 4, 5, 6, b1_2, b2_2, bh, nullptr, out);
}